// round 12
// baseline (speedup 1.0000x reference)
#include <cuda_runtime.h>
#include <cstdint>

// out = X @ G + bias with G = TT(g0,g1,g2). Structured contraction:
//   Stage1: A[n][k*64+a]   = sum_ij X[n][ij*16+k] * g0[ij*64+a]
//   Stage2: B[n][l*64+b]   = sum_ka A[n][k*64+a] * W1[(k*64+a)][(l*64+b)]
//   Stage3: out[n][l*256+mn] = sum_b B[n][l*64+b] * g2[b*256+mn] + bias
// All fp32 exact; inner loops use packed fma.rn.f32x2 (Blackwell FFMA2).

typedef unsigned long long u64;

__device__ float g_A[(size_t)8192 * 1024];
__device__ float g_B[(size_t)8192 * 1024];
__device__ float g_W1[1024 * 1024];

__device__ __forceinline__ u64 pk2(float x, float y) {
    u64 r; asm("mov.b64 %0, {%1, %2};" : "=l"(r) : "f"(x), "f"(y)); return r;
}
__device__ __forceinline__ void fma2(u64 &d, u64 a, u64 b) {
    asm("fma.rn.f32x2 %0, %1, %2, %0;" : "+l"(d) : "l"(a), "l"(b));
}

// ---------------------------------------------------------------------------
// Reorder g1[a][k][l][b] -> W1[(k*64+a)][(l*64+b)]   (1024x1024)
// ---------------------------------------------------------------------------
__global__ void k_reorder(const float* __restrict__ g1) {
    int idx = blockIdx.x * 256 + threadIdx.x;   // source linear index
    int b = idx & 63;
    int l = (idx >> 6) & 15;
    int k = (idx >> 10) & 15;
    int a = idx >> 14;
    g_W1[(k * 64 + a) * 1024 + l * 64 + b] = g1[idx];
}

// ---------------------------------------------------------------------------
// Stage 1: grid 4096 blocks x 256 thr, 2 rows/block.
// thread -> (k = tid>>4, a-group ag = tid&15, a in [4*ag, 4*ag+4))
// ---------------------------------------------------------------------------
__global__ __launch_bounds__(256) void k_stage1(const float* __restrict__ X,
                                                const float* __restrict__ g0) {
    __shared__ float Xs[2][4096];
    __shared__ float M0s[32][64];
    int tid = threadIdx.x;
    int row0 = blockIdx.x * 2;
    #pragma unroll
    for (int r = 0; r < 2; r++)
        for (int c = tid; c < 4096; c += 256)
            Xs[r][c] = X[(size_t)(row0 + r) * 4096 + c];

    int k  = tid >> 4;
    int ag = tid & 15;
    alignas(16) u64 acc[2][2] = {};

    for (int ij0 = 0; ij0 < 256; ij0 += 32) {
        __syncthreads();
        for (int t = tid; t < 2048; t += 256)
            M0s[t >> 6][t & 63] = g0[(ij0 + (t >> 6)) * 64 + (t & 63)];
        __syncthreads();
        #pragma unroll
        for (int u = 0; u < 32; u++) {
            u64 m0 = *(const u64*)&M0s[u][ag * 4];
            u64 m1 = *(const u64*)&M0s[u][ag * 4 + 2];
            #pragma unroll
            for (int r = 0; r < 2; r++) {
                float xv = Xs[r][(ij0 + u) * 16 + k];
                u64 x2 = pk2(xv, xv);
                fma2(acc[r][0], x2, m0);
                fma2(acc[r][1], x2, m1);
            }
        }
    }
    #pragma unroll
    for (int r = 0; r < 2; r++)
        *(float4*)&g_A[(size_t)(row0 + r) * 1024 + k * 64 + ag * 4] =
            *(float4*)&acc[r][0];
}

// ---------------------------------------------------------------------------
// Stage 2: SGEMM 8192x1024x1024. 128x128 block tile, 16-wide K tile,
// 256 threads, 8x8 per-thread tile, FFMA2 inner product, reg prefetch.
// ---------------------------------------------------------------------------
__global__ __launch_bounds__(256) void k_stage2() {
    __shared__ float As[16][128];   // [k][m]
    __shared__ float Bs[16][128];   // [k][n]
    int tid = threadIdx.x;
    int m0 = blockIdx.y * 128;
    int n0 = blockIdx.x * 128;
    int ty = tid >> 4, tx = tid & 15;

    int ar[2], aq[2], br[2], bc[2];
    #pragma unroll
    for (int i = 0; i < 2; i++) {
        int idx = tid + 256 * i;
        ar[i] = idx >> 2;  aq[i] = (idx & 3) * 4;
        br[i] = idx >> 5;  bc[i] = (idx & 31) * 4;
    }

    float4 pa[2], pb[2];
    #pragma unroll
    for (int i = 0; i < 2; i++) {
        pa[i] = *(const float4*)&g_A[(size_t)(m0 + ar[i]) * 1024 + aq[i]];
        pb[i] = *(const float4*)&g_W1[(size_t)br[i] * 1024 + n0 + bc[i]];
    }
    #pragma unroll
    for (int i = 0; i < 2; i++) {
        As[aq[i] + 0][ar[i]] = pa[i].x;
        As[aq[i] + 1][ar[i]] = pa[i].y;
        As[aq[i] + 2][ar[i]] = pa[i].z;
        As[aq[i] + 3][ar[i]] = pa[i].w;
        *(float4*)&Bs[br[i]][bc[i]] = pb[i];
    }
    __syncthreads();

    alignas(16) u64 acc[8][4] = {};

    for (int kt = 0; kt < 64; kt++) {
        if (kt < 63) {
            #pragma unroll
            for (int i = 0; i < 2; i++) {
                pa[i] = *(const float4*)&g_A[(size_t)(m0 + ar[i]) * 1024 +
                                             (kt + 1) * 16 + aq[i]];
                pb[i] = *(const float4*)&g_W1[(size_t)((kt + 1) * 16 + br[i]) * 1024 +
                                              n0 + bc[i]];
            }
        }
        #pragma unroll
        for (int k = 0; k < 16; k++) {
            float4 a0 = *(const float4*)&As[k][ty * 8];
            float4 a1 = *(const float4*)&As[k][ty * 8 + 4];
            u64 b0 = *(const u64*)&Bs[k][tx * 8];
            u64 b1 = *(const u64*)&Bs[k][tx * 8 + 2];
            u64 b2 = *(const u64*)&Bs[k][tx * 8 + 4];
            u64 b3 = *(const u64*)&Bs[k][tx * 8 + 6];
            float av[8] = {a0.x, a0.y, a0.z, a0.w, a1.x, a1.y, a1.z, a1.w};
            #pragma unroll
            for (int i = 0; i < 8; i++) {
                u64 a2 = pk2(av[i], av[i]);
                fma2(acc[i][0], a2, b0);
                fma2(acc[i][1], a2, b1);
                fma2(acc[i][2], a2, b2);
                fma2(acc[i][3], a2, b3);
            }
        }
        __syncthreads();
        if (kt < 63) {
            #pragma unroll
            for (int i = 0; i < 2; i++) {
                As[aq[i] + 0][ar[i]] = pa[i].x;
                As[aq[i] + 1][ar[i]] = pa[i].y;
                As[aq[i] + 2][ar[i]] = pa[i].z;
                As[aq[i] + 3][ar[i]] = pa[i].w;
                *(float4*)&Bs[br[i]][bc[i]] = pb[i];
            }
            __syncthreads();
        }
    }
    #pragma unroll
    for (int i = 0; i < 8; i++) {
        size_t o = (size_t)(m0 + ty * 8 + i) * 1024 + n0 + tx * 8;
        *(float4*)&g_B[o]     = *(float4*)&acc[i][0];
        *(float4*)&g_B[o + 4] = *(float4*)&acc[i][2];
    }
}

// ---------------------------------------------------------------------------
// Stage 3: per block: 64 rows x 256 cols for one l. K=64 (chunks of 16).
// thread -> rows [ty*8, ty*8+8), cols {lane + 32*j}, row-paired FFMA2.
// ---------------------------------------------------------------------------
__global__ __launch_bounds__(256) void k_stage3(const float* __restrict__ g2,
                                                const float* __restrict__ bias,
                                                float* __restrict__ out) {
    __shared__ float W2s[16][256];
    __shared__ float Bs[64][20];   // padded rows
    int tid  = threadIdx.x;
    int n0   = blockIdx.x * 64;
    int l    = blockIdx.y;
    int ty   = tid >> 5;
    int lane = tid & 31;

    alignas(16) u64 acc[4][8] = {};

    for (int kc = 0; kc < 4; kc++) {
        __syncthreads();
        #pragma unroll
        for (int i = 0; i < 4; i++) {
            int t4 = tid + i * 256;
            int r = t4 >> 6, c = (t4 & 63) * 4;
            *(float4*)&W2s[r][c] = *(const float4*)&g2[(kc * 16 + r) * 256 + c];
        }
        {
            int r = tid >> 2, c = (tid & 3) * 4;
            *(float4*)&Bs[r][c] =
                *(const float4*)&g_B[(size_t)(n0 + r) * 1024 + l * 64 + kc * 16 + c];
        }
        __syncthreads();
        #pragma unroll
        for (int k = 0; k < 16; k++) {
            u64 w2[8];
            #pragma unroll
            for (int j = 0; j < 8; j++) {
                float w = W2s[k][lane + 32 * j];
                w2[j] = pk2(w, w);
            }
            #pragma unroll
            for (int p = 0; p < 4; p++) {
                u64 bp = pk2(Bs[ty * 8 + 2 * p][k], Bs[ty * 8 + 2 * p + 1][k]);
                #pragma unroll
                for (int j = 0; j < 8; j++)
                    fma2(acc[p][j], bp, w2[j]);
            }
        }
    }

    #pragma unroll
    for (int j = 0; j < 8; j++) {
        int col = l * 256 + lane + 32 * j;
        float bb = bias[col];
        #pragma unroll
        for (int p = 0; p < 4; p++) {
            float2 v = *(float2*)&acc[p][j];
            out[(size_t)(n0 + ty * 8 + 2 * p) * 4096 + col]     = v.x + bb;
            out[(size_t)(n0 + ty * 8 + 2 * p + 1) * 4096 + col] = v.y + bb;
        }
    }
}

// ---------------------------------------------------------------------------
extern "C" void kernel_launch(void* const* d_in, const int* in_sizes, int n_in,
                              void* d_out, int out_size) {
    const float* x    = (const float*)d_in[0];   // (4,2048,4096)
    const float* g0   = (const float*)d_in[1];   // (1,16,16,64)
    const float* g1   = (const float*)d_in[2];   // (64,16,16,64)
    const float* g2   = (const float*)d_in[3];   // (64,16,16,1)
    const float* bias = (const float*)d_in[4];   // (4096,)
    float* out = (float*)d_out;                  // (8192,4096)

    k_reorder<<<4096, 256>>>(g1);                 // 1M elems
    k_stage1 <<<4096, 256>>>(x, g0);              // 8192 rows / 2
    k_stage2 <<<dim3(8, 64), 256>>>();            // 1024/128 x 8192/128
    k_stage3 <<<dim3(128, 16), 256>>>(g2, bias, out); // 8192/64 x 16 l-slices
}